// round 11
// baseline (speedup 1.0000x reference)
#include <cuda_runtime.h>

// TP_nonlinearity: B=512, MUL=64, dims {0:1, 1:3, 2:5}
// out0: [512,12288,1]  blocks: (0,0)@0, (1,1)@4096, (2,2)@8192
// out1: [512,16384,3]  blocks: (0,1)@0, (1,1)@4096, (1,2)@8192, (2,2)@12288
// out2: [512,16384,5]  blocks: (0,2)@0, (1,1)@4096, (1,2)@8192, (2,2)@12288
//
// Grid 2048 = 4 CTAs per batch element, split by triple set; each CTA emits
// all 64 rows of its set (z reused across 4 stores).
//   set0: (0,2,2) (1,2,1) (0,0,0)
//   set1: (1,1,2) (0,1,1) (1,1,0)
//   set2: (1,2,2) (2,2,1) (2,2,0)
//   set3: (2,2,2) (1,1,1)
// launch_bounds(256,6): regs<=42 -> 6 CTAs/SM (48 warps, 75% occ cap).

struct Params {
    const float* x0; const float* x1; const float* x2;
    const float* w[11];
    float* o0; float* o1; float* o2;
};

// ---------------- stage 1: slot-major z ----------------
// zc4[ZB4 + m*16*D3 + w].c = sum_n w[m,n,M(4w+c)] * x_{l2}[j(4w+c), n]
template<int D1, int D2, int D3, int ZB4, int XO>
__device__ __forceinline__ void stage1(const float* __restrict__ w,
                                       float4* __restrict__ zc4,
                                       const float* __restrict__ xs, int tid) {
    constexpr int NT = D1 * 16 * D3;
#pragma unroll 1
    for (int task = tid; task < NT; task += 256) {
        const int m  = task / (16 * D3);
        const int ww = task - m * (16 * D3);
        const float* wrow = w + m * D2 * D3;
        float out[4];
#pragma unroll
        for (int c = 0; c < 4; ++c) {
            const int rem = 4 * ww + c;
            const int j = rem / D3;
            const int M = rem - j * D3;
            const float* xr = xs + XO + j * D2;
            float acc = 0.f;
#pragma unroll
            for (int n = 0; n < D2; ++n)
                acc = fmaf(__ldg(wrow + n * D3 + M), xr[n], acc);
            out[c] = acc;
        }
        float4 v; v.x = out[0]; v.y = out[1]; v.z = out[2]; v.w = out[3];
        zc4[ZB4 + m * (16 * D3) + ww] = v;
    }
}

// ---------------- stage 2: vectorized z, direct float4 output ----------------
// slot s = q*256+tid; w = s mod 16*D3; ii = s / (16*D3); 4 chunks of 16 rows.
template<int D1, int D3, int ZB4, int XO>
__device__ __forceinline__ void proc(float* __restrict__ outp,
                                     const float4* __restrict__ zc4,
                                     const float* __restrict__ xs,
                                     int tid) {
    float4* __restrict__ o4 = reinterpret_cast<float4*>(outp);
#pragma unroll 1
    for (int q = 0; q < D3; ++q) {
        const int s  = q * 256 + tid;
        const int ii = s / (16 * D3);
        const int w  = s - ii * (16 * D3);

        float4 zm[D1];
#pragma unroll
        for (int m = 0; m < D1; ++m)
            zm[m] = zc4[ZB4 + m * (16 * D3) + w];

#pragma unroll
        for (int ci = 0; ci < 4; ++ci) {
            const int i = ci * 16 + ii;
            float4 v;
            {
                const float xv0 = xs[XO + i * D1];
                v.x = xv0 * zm[0].x;
                v.y = xv0 * zm[0].y;
                v.z = xv0 * zm[0].z;
                v.w = xv0 * zm[0].w;
            }
#pragma unroll
            for (int m = 1; m < D1; ++m) {
                const float xv = xs[XO + i * D1 + m];
                v.x = fmaf(xv, zm[m].x, v.x);
                v.y = fmaf(xv, zm[m].y, v.y);
                v.z = fmaf(xv, zm[m].z, v.z);
                v.w = fmaf(xv, zm[m].w, v.w);
            }
            __stcs(o4 + ci * (256 * D3) + s, v);
        }
    }
}

__global__ __launch_bounds__(256, 6) void tp_kernel(Params P) {
    __shared__ float  xs[64 * 9];     // x0:[0,64) | x1:[64,256) | x2:[256,576)
    __shared__ float4 zc4[1680];      // slot-major z (global offsets; CTA touches its set)

    const int tid = threadIdx.x;
    const int b   = blockIdx.x >> 2;
    const int set = blockIdx.x & 3;

    for (int e = tid; e < 64;  e += 256) xs[e]       = P.x0[b * 64  + e];
    for (int e = tid; e < 192; e += 256) xs[64 + e]  = P.x1[b * 192 + e];
    for (int e = tid; e < 320; e += 256) xs[256 + e] = P.x2[b * 320 + e];
    __syncthreads();

    const size_t bo0 = (size_t)b * 12288;
    const size_t bo1 = (size_t)b * 16384;

    if (set == 0) {
        // (0,2,2) (1,2,1) (0,0,0)
        stage1<1,5,5,   64, 256>(P.w[2],  zc4, xs, tid);
        stage1<3,5,3,  576, 256>(P.w[6],  zc4, xs, tid);
        stage1<1,1,1,    0,   0>(P.w[0],  zc4, xs, tid);
        __syncthreads();
        proc<1,5,   64,   0>(P.o2 + (bo1)         * 5,   zc4, xs, tid);
        proc<3,3,  576,  64>(P.o1 + (bo1 + 8192)  * 3,   zc4, xs, tid);
        proc<1,1,    0,   0>(P.o0 + bo0,                 zc4, xs, tid);
    } else if (set == 1) {
        // (1,1,2) (0,1,1) (1,1,0)
        stage1<3,3,5,  336,  64>(P.w[5],  zc4, xs, tid);
        stage1<1,3,3,   16,  64>(P.w[1],  zc4, xs, tid);
        stage1<3,3,1,  144,  64>(P.w[3],  zc4, xs, tid);
        __syncthreads();
        proc<3,5,  336,  64>(P.o2 + (bo1 + 4096)  * 5,   zc4, xs, tid);
        proc<1,3,   16,   0>(P.o1 + (bo1)         * 3,   zc4, xs, tid);
        proc<3,1,  144,  64>(P.o0 + bo0 + 4096,          zc4, xs, tid);
    } else if (set == 2) {
        // (1,2,2) (2,2,1) (2,2,0)
        stage1<3,5,5,  720, 256>(P.w[7],  zc4, xs, tid);
        stage1<5,5,3, 1040, 256>(P.w[9],  zc4, xs, tid);
        stage1<5,5,1,  960, 256>(P.w[8],  zc4, xs, tid);
        __syncthreads();
        proc<3,5,  720,  64>(P.o2 + (bo1 + 8192)  * 5,   zc4, xs, tid);
        proc<5,3, 1040, 256>(P.o1 + (bo1 + 12288) * 3,   zc4, xs, tid);
        proc<5,1,  960, 256>(P.o0 + bo0 + 8192,          zc4, xs, tid);
    } else {
        // (2,2,2) (1,1,1)
        stage1<5,5,5, 1280, 256>(P.w[10], zc4, xs, tid);
        stage1<3,3,3,  192,  64>(P.w[4],  zc4, xs, tid);
        __syncthreads();
        proc<5,5, 1280, 256>(P.o2 + (bo1 + 12288) * 5,   zc4, xs, tid);
        proc<3,3,  192,  64>(P.o1 + (bo1 + 4096)  * 3,   zc4, xs, tid);
    }
}

extern "C" void kernel_launch(void* const* d_in, const int* in_sizes, int n_in,
                              void* d_out, int out_size) {
    Params P;
    P.x0 = (const float*)d_in[0];
    P.x1 = (const float*)d_in[1];
    P.x2 = (const float*)d_in[2];
    for (int t = 0; t < 11; ++t) P.w[t] = (const float*)d_in[3 + t];
    float* out = (float*)d_out;
    P.o0 = out;
    P.o1 = out + (size_t)512 * 12288;
    P.o2 = out + (size_t)512 * 12288 + (size_t)512 * 16384 * 3;
    tp_kernel<<<2048, 256>>>(P);
}

// round 12
// speedup vs baseline: 1.0745x; 1.0745x over previous
#include <cuda_runtime.h>

// TP_nonlinearity: B=512, MUL=64, dims {0:1, 1:3, 2:5}
// out0: [512,12288,1]  blocks: (0,0)@0, (1,1)@4096, (2,2)@8192
// out1: [512,16384,3]  blocks: (0,1)@0, (1,1)@4096, (1,2)@8192, (2,2)@12288
// out2: [512,16384,5]  blocks: (0,2)@0, (1,1)@4096, (1,2)@8192, (2,2)@12288
//
// Grid 4096 = 8 CTAs per batch element (fine granularity kills the
// drain-wave tail). Each CTA emits all 64 rows of its triple set:
//   s0:(0,2,2)  s1:(1,1,2)  s2:(1,2,2)  s3:(2,2,2)
//   s4:(0,1,1)+(0,0,0)  s5:(1,1,1)+(1,1,0)  s6:(1,2,1)+(2,2,0)  s7:(2,2,1)
// launch_bounds(256,6): regs<=42 -> 6 CTAs/SM.

struct Params {
    const float* x0; const float* x1; const float* x2;
    const float* w[11];
    float* o0; float* o1; float* o2;
};

// ---------------- stage 1: slot-major z ----------------
// zc4[ZB4 + m*16*D3 + w].c = sum_n w[m,n,M(4w+c)] * x_{l2}[j(4w+c), n]
template<int D1, int D2, int D3, int ZB4, int XO>
__device__ __forceinline__ void stage1(const float* __restrict__ w,
                                       float4* __restrict__ zc4,
                                       const float* __restrict__ xs, int tid) {
    constexpr int NT = D1 * 16 * D3;
#pragma unroll 1
    for (int task = tid; task < NT; task += 256) {
        const int m  = task / (16 * D3);
        const int ww = task - m * (16 * D3);
        const float* wrow = w + m * D2 * D3;
        float out[4];
#pragma unroll
        for (int c = 0; c < 4; ++c) {
            const int rem = 4 * ww + c;
            const int j = rem / D3;
            const int M = rem - j * D3;
            const float* xr = xs + XO + j * D2;
            float acc = 0.f;
#pragma unroll
            for (int n = 0; n < D2; ++n)
                acc = fmaf(__ldg(wrow + n * D3 + M), xr[n], acc);
            out[c] = acc;
        }
        float4 v; v.x = out[0]; v.y = out[1]; v.z = out[2]; v.w = out[3];
        zc4[ZB4 + m * (16 * D3) + ww] = v;
    }
}

// ---------------- stage 2: vectorized z, direct float4 output ----------------
// slot s = q*256+tid; w = s mod 16*D3; ii = s / (16*D3); 4 chunks of 16 rows.
template<int D1, int D3, int ZB4, int XO>
__device__ __forceinline__ void proc(float* __restrict__ outp,
                                     const float4* __restrict__ zc4,
                                     const float* __restrict__ xs,
                                     int tid) {
    float4* __restrict__ o4 = reinterpret_cast<float4*>(outp);
#pragma unroll 1
    for (int q = 0; q < D3; ++q) {
        const int s  = q * 256 + tid;
        const int ii = s / (16 * D3);
        const int w  = s - ii * (16 * D3);

        float4 zm[D1];
#pragma unroll
        for (int m = 0; m < D1; ++m)
            zm[m] = zc4[ZB4 + m * (16 * D3) + w];

#pragma unroll
        for (int ci = 0; ci < 4; ++ci) {
            const int i = ci * 16 + ii;
            float4 v;
            {
                const float xv0 = xs[XO + i * D1];
                v.x = xv0 * zm[0].x;
                v.y = xv0 * zm[0].y;
                v.z = xv0 * zm[0].z;
                v.w = xv0 * zm[0].w;
            }
#pragma unroll
            for (int m = 1; m < D1; ++m) {
                const float xv = xs[XO + i * D1 + m];
                v.x = fmaf(xv, zm[m].x, v.x);
                v.y = fmaf(xv, zm[m].y, v.y);
                v.z = fmaf(xv, zm[m].z, v.z);
                v.w = fmaf(xv, zm[m].w, v.w);
            }
            __stcs(o4 + ci * (256 * D3) + s, v);
        }
    }
}

__global__ __launch_bounds__(256, 6) void tp_kernel(Params P) {
    __shared__ float  xs[64 * 9];     // x0:[0,64) | x1:[64,256) | x2:[256,576)
    __shared__ float4 zc4[1680];      // slot-major z (global offsets; CTA touches its set)

    const int tid = threadIdx.x;
    const int b   = blockIdx.x >> 3;
    const int set = blockIdx.x & 7;

    for (int e = tid; e < 64;  e += 256) xs[e]       = P.x0[b * 64  + e];
    for (int e = tid; e < 192; e += 256) xs[64 + e]  = P.x1[b * 192 + e];
    for (int e = tid; e < 320; e += 256) xs[256 + e] = P.x2[b * 320 + e];
    __syncthreads();

    const size_t bo0 = (size_t)b * 12288;
    const size_t bo1 = (size_t)b * 16384;

    switch (set) {
    case 0:  // (0,2,2)
        stage1<1,5,5,   64, 256>(P.w[2],  zc4, xs, tid);
        __syncthreads();
        proc<1,5,   64,   0>(P.o2 + (bo1)         * 5,   zc4, xs, tid);
        break;
    case 1:  // (1,1,2)
        stage1<3,3,5,  336,  64>(P.w[5],  zc4, xs, tid);
        __syncthreads();
        proc<3,5,  336,  64>(P.o2 + (bo1 + 4096)  * 5,   zc4, xs, tid);
        break;
    case 2:  // (1,2,2)
        stage1<3,5,5,  720, 256>(P.w[7],  zc4, xs, tid);
        __syncthreads();
        proc<3,5,  720,  64>(P.o2 + (bo1 + 8192)  * 5,   zc4, xs, tid);
        break;
    case 3:  // (2,2,2)
        stage1<5,5,5, 1280, 256>(P.w[10], zc4, xs, tid);
        __syncthreads();
        proc<5,5, 1280, 256>(P.o2 + (bo1 + 12288) * 5,   zc4, xs, tid);
        break;
    case 4:  // (0,1,1) + (0,0,0)
        stage1<1,3,3,   16,  64>(P.w[1],  zc4, xs, tid);
        stage1<1,1,1,    0,   0>(P.w[0],  zc4, xs, tid);
        __syncthreads();
        proc<1,3,   16,   0>(P.o1 + (bo1)         * 3,   zc4, xs, tid);
        proc<1,1,    0,   0>(P.o0 + bo0,                 zc4, xs, tid);
        break;
    case 5:  // (1,1,1) + (1,1,0)
        stage1<3,3,3,  192,  64>(P.w[4],  zc4, xs, tid);
        stage1<3,3,1,  144,  64>(P.w[3],  zc4, xs, tid);
        __syncthreads();
        proc<3,3,  192,  64>(P.o1 + (bo1 + 4096)  * 3,   zc4, xs, tid);
        proc<3,1,  144,  64>(P.o0 + bo0 + 4096,          zc4, xs, tid);
        break;
    case 6:  // (1,2,1) + (2,2,0)
        stage1<3,5,3,  576, 256>(P.w[6],  zc4, xs, tid);
        stage1<5,5,1,  960, 256>(P.w[8],  zc4, xs, tid);
        __syncthreads();
        proc<3,3,  576,  64>(P.o1 + (bo1 + 8192)  * 3,   zc4, xs, tid);
        proc<5,1,  960, 256>(P.o0 + bo0 + 8192,          zc4, xs, tid);
        break;
    default: // (2,2,1)
        stage1<5,5,3, 1040, 256>(P.w[9],  zc4, xs, tid);
        __syncthreads();
        proc<5,3, 1040, 256>(P.o1 + (bo1 + 12288) * 3,   zc4, xs, tid);
        break;
    }
}

extern "C" void kernel_launch(void* const* d_in, const int* in_sizes, int n_in,
                              void* d_out, int out_size) {
    Params P;
    P.x0 = (const float*)d_in[0];
    P.x1 = (const float*)d_in[1];
    P.x2 = (const float*)d_in[2];
    for (int t = 0; t < 11; ++t) P.w[t] = (const float*)d_in[3 + t];
    float* out = (float*)d_out;
    P.o0 = out;
    P.o1 = out + (size_t)512 * 12288;
    P.o2 = out + (size_t)512 * 12288 + (size_t)512 * 16384 * 3;
    tp_kernel<<<4096, 256>>>(P);
}